// round 10
// baseline (speedup 1.0000x reference)
#include <cuda_runtime.h>
#include <cuda_pipeline.h>
#include <cstdint>

// Problem constants (fixed by the reference)
#define B 16
#define S 4096
#define H 768
#define NUM_WORDS 2048          // S/2
#define H4 (H / 4)              // 192 float4 lanes per row
#define TT 32                   // tokens owned per chunk
#define NT 128                  // chunks per batch row (covers tokens 1..4095)
#define NCHUNKS (B * NT)        // 2048 total chunks
#define WW (NUM_WORDS / NT)     // 16: static zero-fill words per chunk
#define T 6                     // tokens per pipeline stage
#define STG_F4 (T * H4)         // float4 elements per stage (1152 = 18KB)
#define WIN (TT + 2)            // wid window: positions t0-1 .. t0+TT
#define GRID 888                // 148 SMs x 6 resident blocks: one exact wave

// Persistent fused kernel. Each block grid-strides over chunks. Chunk (b, tc)
// owns token range [t0, t0+TT):
//  1. loads its word_ids window (static addresses),
//  2. warp 0 finds words STARTING in the range (ballot/popc/ffs) + their ends,
//  3. streams tokens [s_first, e_last) through a 2-stage cp.async pipeline,
//     routing tokens to consecutive word accumulators via the smem end table,
//  4. zero-fills its static word slot for words > wmax.
// Word ids are non-decreasing and contiguous from 0 per row, so runs are
// contiguous and every output word is written exactly once.
__global__ __launch_bounds__(H4) void fused_word_mean_kernel(
    const float* __restrict__ hidden,   // [B, S, H]
    const int*   __restrict__ word_ids, // [B, S]
    float*       __restrict__ out)      // [B, NUM_WORDS, H]
{
    __shared__ float4 s_buf[2][STG_F4];     // 36 KB
    __shared__ int s_wid[WIN];
    __shared__ int s_endtab[TT];
    __shared__ int s_meta[4];               // nwords, s_first, w_first, e_last

    const int tid = threadIdx.x;            // 0..191

    for (int chunk = blockIdx.x; chunk < NCHUNKS; chunk += GRID) {
        const int b  = chunk / NT;
        const int tc = chunk % NT;
        const int t0 = 1 + tc * TT;
        const int t_range_end = min(t0 + TT, S - 1);
        const int* __restrict__ wrow = word_ids + b * S;

        // ---- load wid window [t0-1 .. t0+TT] ----
        if (tid < WIN) {
            const int p = t0 - 1 + tid;
            s_wid[tid] = (p < S) ? wrow[p] : -1;
        }
        __syncthreads();

        // ---- warp 0: build local boundary table ----
        if (tid < 32) {
            const int i = tid;               // token p = t0 + i
            const int p = t0 + i;
            const int w_i    = s_wid[i + 1];
            const int prev_i = s_wid[i];
            const bool is_start = (p < t_range_end) && (w_i != prev_i);
            const unsigned mask = __ballot_sync(0xffffffffu, is_start);
            const int nwords = __popc(mask);
            if (is_start) {
                const int rank = __popc(mask & ((1u << i) - 1));
                int end;
                const unsigned higher = mask & ~((i < 31) ? ((2u << i) - 1) : 0xffffffffu);
                if (higher) {
                    end = t0 + __ffs(higher) - 1;   // next start = this word's end
                } else {
                    // last word starting in range: scan forward (terminates at
                    // latest at wid[S-1] == -1)
                    int q = p + 1;
                    while (true) {
                        const int wi = q - (t0 - 1);
                        const int wq = (wi < WIN) ? s_wid[wi] : __ldg(wrow + q);
                        if (wq != w_i) break;
                        ++q;
                    }
                    end = q;
                }
                s_endtab[rank] = end;
                if (rank == 0) { s_meta[1] = p; s_meta[2] = w_i; }
                if (rank == nwords - 1) s_meta[3] = end;
            }
            if (i == 0) s_meta[0] = nwords;
        }
        __syncthreads();

        const int nwords = s_meta[0];

        if (nwords > 0) {
            const int s_first = s_meta[1];
            const int w_first = s_meta[2];
            const int e_last  = s_meta[3];
            const int n_tok   = e_last - s_first;

            const float4* __restrict__ src =
                reinterpret_cast<const float4*>(hidden) + ((size_t)b * S + s_first) * H4;
            float4* __restrict__ outBase =
                reinterpret_cast<float4*>(out) + ((size_t)b * NUM_WORDS + w_first) * H4 + tid;

            const int total_f4 = n_tok * H4;
            const int n_stages = (n_tok + T - 1) / T;

            // ---- issue stage 0 ----
            #pragma unroll
            for (int i = 0; i < T; ++i) {
                const int idx = i * H4 + tid;
                if (idx < total_f4)
                    __pipeline_memcpy_async(&s_buf[0][idx], &src[idx], sizeof(float4));
            }
            __pipeline_commit();

            int k = 0;
            int e_cur = s_endtab[0];
            int s_cur = s_first;
            float4 acc = make_float4(0.f, 0.f, 0.f, 0.f);

            for (int s = 0; s < n_stages; ++s) {
                if (s + 1 < n_stages) {
                    float4* dst = s_buf[(s + 1) & 1];
                    const int base = (s + 1) * STG_F4;
                    #pragma unroll
                    for (int i = 0; i < T; ++i) {
                        const int idx = i * H4 + tid;
                        const int g   = base + idx;
                        if (g < total_f4)
                            __pipeline_memcpy_async(&dst[idx], &src[g], sizeof(float4));
                    }
                    __pipeline_commit();
                    __pipeline_wait_prior(1);
                } else {
                    __pipeline_wait_prior(0);
                }
                __syncthreads();

                const float4* __restrict__ buf = s_buf[s & 1];
                #pragma unroll
                for (int j = 0; j < T; ++j) {
                    const int t = s_first + s * T + j;
                    if (t < e_last) {        // uniform across block
                        const float4 v = buf[j * H4 + tid];
                        if (t == e_cur) {    // word k complete -> emit mean
                            const int c = e_cur - s_cur;
                            const float inv = __fdividef(1.0f, (float)c);
                            float4 r;
                            r.x = acc.x * inv; r.y = acc.y * inv;
                            r.z = acc.z * inv; r.w = acc.w * inv;
                            outBase[k * H4] = r;
                            s_cur = e_cur;
                            ++k;
                            e_cur = s_endtab[k < nwords ? k : nwords - 1];
                            acc = make_float4(0.f, 0.f, 0.f, 0.f);
                        }
                        acc.x += v.x; acc.y += v.y;
                        acc.z += v.z; acc.w += v.w;
                    }
                }
                __syncthreads();   // protect buf[s&1] before stage s+2 overwrites it
            }

            // Last word (its end == e_last is never reached inside the loop).
            {
                const int c = e_last - s_cur;
                const float inv = __fdividef(1.0f, (float)(c > 0 ? c : 1));
                float4 r;
                r.x = acc.x * inv; r.y = acc.y * inv;
                r.z = acc.z * inv; r.w = acc.w * inv;
                outBase[(nwords - 1) * H4] = r;
            }
        }

        // ---- static zero-fill for absent words (w > wmax) in this slot ----
        const int wmax = __ldg(wrow + (S - 2));
        const int wz0  = tc * WW;
        if (wz0 + WW - 1 > wmax) {
            float4* __restrict__ zrow =
                reinterpret_cast<float4*>(out) + (size_t)b * NUM_WORDS * H4 + tid;
            const float4 z = make_float4(0.f, 0.f, 0.f, 0.f);
            #pragma unroll
            for (int k2 = 0; k2 < WW; ++k2) {
                const int w = wz0 + k2;
                if (w > wmax) zrow[(size_t)w * H4] = z;
            }
        }

        // Laggards finish register-only epilogue before next chunk's warp 0
        // rewrites s_wid/s_endtab only after the first barrier of the next
        // iteration; the s_wid store below that barrier is the only overlap,
        // and it touches memory no epilogue reads. Sync to be explicit.
        __syncthreads();
    }
}

extern "C" void kernel_launch(void* const* d_in, const int* in_sizes, int n_in,
                              void* d_out, int out_size)
{
    const float* hidden   = (const float*)d_in[0];  // [B,S,H] float32
    const int*   word_ids = (const int*)d_in[1];    // [B,S] int32
    float*       out      = (float*)d_out;          // [B,NUM_WORDS,H] float32

    (void)in_sizes; (void)n_in; (void)out_size;

    fused_word_mean_kernel<<<GRID, H4>>>(hidden, word_ids, out);
}

// round 11
// speedup vs baseline: 1.0118x; 1.0118x over previous
#include <cuda_runtime.h>
#include <cuda_pipeline.h>
#include <cstdint>

// Problem constants (fixed by the reference)
#define B 16
#define S 4096
#define H 768
#define NUM_WORDS 2048          // S/2
#define H4 (H / 4)              // 192 float4 lanes per row
#define TT 32                   // tokens owned per block
#define NT 128                  // blocks per batch row (covers tokens 1..4095)
#define WW (NUM_WORDS / NT)     // 16: static zero-fill words per block
#define T 6                     // tokens per pipeline stage
#define STG_F4 (T * H4)         // float4 elements per stage (1152 = 18KB)
#define WIN (TT + 2)            // wid window: positions t0-1 .. t0+TT

// Fused single kernel, one block per (batch, 32-token chunk).
// Payload pipeline is fully PER-THREAD: each thread's cp.async writes only
// smem cells {j*H4 + tid} and only that thread reads them, so no barriers are
// needed in the streaming loop — each thread waits only on its own groups.
__global__ __launch_bounds__(H4) void fused_word_mean_kernel(
    const float* __restrict__ hidden,   // [B, S, H]
    const int*   __restrict__ word_ids, // [B, S]
    float*       __restrict__ out)      // [B, NUM_WORDS, H]
{
    __shared__ float4 s_buf[2][STG_F4];     // 36 KB
    __shared__ int s_wid[WIN];
    __shared__ int s_endtab[TT];
    __shared__ int s_meta[4];               // nwords, s_first, w_first, e_last

    const int blk = blockIdx.x;
    const int b   = blk / NT;
    const int tc  = blk % NT;
    const int t0  = 1 + tc * TT;
    const int t_range_end = min(t0 + TT, S - 1);
    const int tid = threadIdx.x;            // 0..191
    const int* __restrict__ wrow = word_ids + b * S;

    // ---- load wid window [t0-1 .. t0+TT] ----
    if (tid < WIN) {
        const int p = t0 - 1 + tid;
        s_wid[tid] = (p < S) ? wrow[p] : -1;
    }
    __syncthreads();

    // ---- warp 0: build local boundary table (words STARTING in range) ----
    if (tid < 32) {
        const int i = tid;                   // token p = t0 + i
        const int p = t0 + i;
        const int w_i    = s_wid[i + 1];
        const int prev_i = s_wid[i];
        const bool is_start = (p < t_range_end) && (w_i != prev_i);
        const unsigned mask = __ballot_sync(0xffffffffu, is_start);
        const int nwords = __popc(mask);
        if (is_start) {
            const int rank = __popc(mask & ((1u << i) - 1));
            int end;
            const unsigned higher = mask & ~((i < 31) ? ((2u << i) - 1) : 0xffffffffu);
            if (higher) {
                end = t0 + __ffs(higher) - 1;     // next start = this word's end
            } else {
                // last word starting in range: scan forward (terminates at
                // latest at wid[S-1] == -1)
                int q = p + 1;
                while (true) {
                    const int wi = q - (t0 - 1);
                    const int wq = (wi < WIN) ? s_wid[wi] : __ldg(wrow + q);
                    if (wq != w_i) break;
                    ++q;
                }
                end = q;
            }
            s_endtab[rank] = end;
            if (rank == 0) { s_meta[1] = p; s_meta[2] = w_i; }
            if (rank == nwords - 1) s_meta[3] = end;
        }
        if (i == 0) s_meta[0] = nwords;
    }
    __syncthreads();    // table ready; ONLY block-wide barrier on the hot path

    const int nwords = s_meta[0];

    if (nwords > 0) {
        const int s_first = s_meta[1];
        const int w_first = s_meta[2];
        const int e_last  = s_meta[3];
        const int n_tok   = e_last - s_first;

        const float4* __restrict__ src =
            reinterpret_cast<const float4*>(hidden) + ((size_t)b * S + s_first) * H4;
        float4* __restrict__ outBase =
            reinterpret_cast<float4*>(out) + ((size_t)b * NUM_WORDS + w_first) * H4 + tid;

        const int total_f4 = n_tok * H4;
        const int n_stages = (n_tok + T - 1) / T;

        // ---- prime the per-thread pipeline: issue stages 0 and 1 ----
        #pragma unroll
        for (int i = 0; i < T; ++i) {
            const int idx = i * H4 + tid;
            if (idx < total_f4)
                __pipeline_memcpy_async(&s_buf[0][idx], &src[idx], sizeof(float4));
        }
        __pipeline_commit();
        if (n_stages > 1) {
            const int base = STG_F4;
            #pragma unroll
            for (int i = 0; i < T; ++i) {
                const int idx = i * H4 + tid;
                const int g   = base + idx;
                if (g < total_f4)
                    __pipeline_memcpy_async(&s_buf[1][idx], &src[g], sizeof(float4));
            }
            __pipeline_commit();
        }

        int k = 0;
        int e_cur = s_endtab[0];
        int s_cur = s_first;
        float4 acc = make_float4(0.f, 0.f, 0.f, 0.f);

        for (int s = 0; s < n_stages; ++s) {
            // wait for THIS thread's stage-s group only
            if (s + 1 < n_stages) __pipeline_wait_prior(1);
            else                  __pipeline_wait_prior(0);

            const float4* __restrict__ buf = s_buf[s & 1];
            #pragma unroll
            for (int j = 0; j < T; ++j) {
                const int t = s_first + s * T + j;
                if (t < e_last) {            // uniform across block
                    const float4 v = buf[j * H4 + tid];
                    if (t == e_cur) {        // word k complete -> emit mean
                        const int c = e_cur - s_cur;
                        const float inv = __fdividef(1.0f, (float)c);
                        float4 r;
                        r.x = acc.x * inv; r.y = acc.y * inv;
                        r.z = acc.z * inv; r.w = acc.w * inv;
                        __stcs(&outBase[k * H4], r);
                        s_cur = e_cur;
                        ++k;
                        e_cur = s_endtab[k < nwords ? k : nwords - 1];
                        acc = make_float4(0.f, 0.f, 0.f, 0.f);
                    }
                    acc.x += v.x; acc.y += v.y;
                    acc.z += v.z; acc.w += v.w;
                }
            }

            // refill buf[s&1] with stage s+2 (this thread's own cells only;
            // its reads above are already retired before the data can land)
            if (s + 2 < n_stages) {
                float4* dst = s_buf[s & 1];
                const int base = (s + 2) * STG_F4;
                #pragma unroll
                for (int i = 0; i < T; ++i) {
                    const int idx = i * H4 + tid;
                    const int g   = base + idx;
                    if (g < total_f4)
                        __pipeline_memcpy_async(&dst[idx], &src[g], sizeof(float4));
                }
                __pipeline_commit();
            }
        }

        // Last word (its end == e_last is never reached inside the loop).
        {
            const int c = e_last - s_cur;
            const float inv = __fdividef(1.0f, (float)(c > 0 ? c : 1));
            float4 r;
            r.x = acc.x * inv; r.y = acc.y * inv;
            r.z = acc.z * inv; r.w = acc.w * inv;
            __stcs(&outBase[(nwords - 1) * H4], r);
        }
    }

    // ---- static zero-fill for absent words (w > wmax) in this block's slot ----
    const int wmax = __ldg(wrow + (S - 2));
    const int wz0  = tc * WW;
    if (wz0 + WW - 1 > wmax) {
        float4* __restrict__ zrow =
            reinterpret_cast<float4*>(out) + (size_t)b * NUM_WORDS * H4 + tid;
        const float4 z = make_float4(0.f, 0.f, 0.f, 0.f);
        #pragma unroll
        for (int k2 = 0; k2 < WW; ++k2) {
            const int w = wz0 + k2;
            if (w > wmax) __stcs(&zrow[(size_t)w * H4], z);
        }
    }
}

extern "C" void kernel_launch(void* const* d_in, const int* in_sizes, int n_in,
                              void* d_out, int out_size)
{
    const float* hidden   = (const float*)d_in[0];  // [B,S,H] float32
    const int*   word_ids = (const int*)d_in[1];    // [B,S] int32
    float*       out      = (float*)d_out;          // [B,NUM_WORDS,H] float32

    (void)in_sizes; (void)n_in; (void)out_size;

    fused_word_mean_kernel<<<B * NT, H4>>>(hidden, word_ids, out);
}